// round 5
// baseline (speedup 1.0000x reference)
#include <cuda_runtime.h>

#define N_NODES  100000
#define N_EDGES  1600000
#define HIDDEN   64
#define N_GRAPHS 64
#define EQ       (N_EDGES / 4)     // 400000 int4 quads

#define NBLK 888                   // 148 SMs * 6 blocks  (residency GUARANTEED by launch_bounds)
#define NTHR 256
#define TOT  (NBLK * NTHR)         // 227328 threads

// ---------------- scratch (zero at load; restored by finalize each call) ----------------
__device__ float  g_deg  [N_NODES];
__device__ float  g_dinv [N_NODES];
__device__ float  g_q    [N_NODES];
__device__ float  g_praw [N_NODES];
__device__ float2 g_ysc  [N_NODES];
__device__ float2 g_araw [N_NODES];
__device__ float  g_stats[2];
__device__ float  g_gsum [2 * N_GRAPHS];
__device__ float  g_gcnt [N_GRAPHS];
__device__ unsigned g_bar[8];

__device__ __forceinline__ void red_add_v2(float2* addr, float a, float b) {
    asm volatile("red.global.add.v2.f32 [%0], {%1, %2};"
                 :: "l"(addr), "f"(a), "f"(b) : "memory");
}
__device__ __forceinline__ float  ldcg(const float* p)  { return __ldcg(p); }
__device__ __forceinline__ float2 ldcg2(const float2* p){ return __ldcg(p); }

// grid-wide barrier: per-phase counter, fence both sides (post-fence IVALLs L1)
__device__ __forceinline__ void gbar(int i) {
    __syncthreads();
    if (threadIdx.x == 0) {
        __threadfence();
        atomicAdd(&g_bar[i], 1u);
        while (*(volatile unsigned*)&g_bar[i] < NBLK) __nanosleep(64);
        __threadfence();
    }
    __syncthreads();
}

__global__ void __launch_bounds__(NTHR, 6)
k_all(const float* __restrict__ x, const int* __restrict__ src,
      const int* __restrict__ dst, const float* __restrict__ ew,
      const int* __restrict__ batch, const float* __restrict__ W1,
      const float* __restrict__ gamma, const float* __restrict__ beta,
      const float* __restrict__ W2, const float* __restrict__ b2,
      float* __restrict__ out)
{
    const int tid = threadIdx.x;
    const int gt0 = blockIdx.x * NTHR + tid;

    __shared__ float sh1[8], sh2[8];
    __shared__ float s_a[HIDDEN], s_b[HIDDEN], s_w0[HIDDEN], s_w1[HIDDEN];
    __shared__ float s_mv[2];
    __shared__ float ssum[2 * N_GRAPHS];
    __shared__ float scnt[N_GRAPHS];

    // ---- P0: deg[dst] += ew ----
    for (int t = gt0; t < EQ; t += TOT) {
        int4   d4 = reinterpret_cast<const int4*>(dst)[t];
        float4 w4 = reinterpret_cast<const float4*>(ew)[t];
        atomicAdd(&g_deg[d4.x], w4.x);
        atomicAdd(&g_deg[d4.y], w4.y);
        atomicAdd(&g_deg[d4.z], w4.z);
        atomicAdd(&g_deg[d4.w], w4.w);
    }
    gbar(0);

    // ---- P1: dinv/q/praw (+ reset deg) ----
    for (int n = gt0; n < N_NODES; n += TOT) {
        float di = rsqrtf(ldcg(&g_deg[n]) + 1.0f);
        float q  = x[n] * di;
        g_dinv[n] = di;
        g_q[n]    = q;
        g_praw[n] = q;
        g_deg[n]  = 0.0f;
    }
    gbar(1);

    // ---- P2: praw[dst] += w * q[src] ----
    for (int t = gt0; t < EQ; t += TOT) {
        int4   s4 = reinterpret_cast<const int4*>(src)[t];
        int4   d4 = reinterpret_cast<const int4*>(dst)[t];
        float4 w4 = reinterpret_cast<const float4*>(ew)[t];
        float q0 = __ldg(&g_q[s4.x]);
        float q1 = __ldg(&g_q[s4.y]);
        float q2 = __ldg(&g_q[s4.z]);
        float q3 = __ldg(&g_q[s4.w]);
        atomicAdd(&g_praw[d4.x], w4.x * q0);
        atomicAdd(&g_praw[d4.y], w4.y * q1);
        atomicAdd(&g_praw[d4.z], w4.z * q2);
        atomicAdd(&g_praw[d4.w], w4.w * q3);
    }
    gbar(2);

    // ---- P3: stats over p = dinv*praw ----
    {
        float s1 = 0.f, s2 = 0.f;
        for (int n = gt0; n < N_NODES; n += TOT) {
            float v = g_dinv[n] * ldcg(&g_praw[n]);
            s1 += v;
            s2 += v * v;
        }
        #pragma unroll
        for (int o = 16; o; o >>= 1) {
            s1 += __shfl_down_sync(0xFFFFFFFFu, s1, o);
            s2 += __shfl_down_sync(0xFFFFFFFFu, s2, o);
        }
        int wid = tid >> 5, lid = tid & 31;
        if (lid == 0) { sh1[wid] = s1; sh2[wid] = s2; }
        __syncthreads();
        if (wid == 0) {
            s1 = (lid < 8) ? sh1[lid] : 0.f;
            s2 = (lid < 8) ? sh2[lid] : 0.f;
            #pragma unroll
            for (int o = 4; o; o >>= 1) {
                s1 += __shfl_down_sync(0xFFFFFFFFu, s1, o);
                s2 += __shfl_down_sync(0xFFFFFFFFu, s2, o);
            }
            if (lid == 0 && (s1 != 0.f || s2 != 0.f)) {
                atomicAdd(&g_stats[0], s1);
                atomicAdd(&g_stats[1], s2);
            }
        }
    }
    gbar(3);

    // ---- P4: BN+ReLU+W2 -> ysc, araw init ----
    {
        if (tid == 0) {
            float mp  = ldcg(&g_stats[0]) * (1.0f / N_NODES);
            float var = ldcg(&g_stats[1]) * (1.0f / N_NODES) - mp * mp;
            s_mv[0] = mp;
            s_mv[1] = var;
        }
        __syncthreads();
        float var = s_mv[1];
        if (tid < HIDDEN) {
            float w1c = W1[tid];
            s_a[tid]  = w1c * rsqrtf(var * w1c * w1c + 1e-5f) * gamma[tid];
            s_b[tid]  = beta[tid];
            s_w0[tid] = W2[2 * tid];
            s_w1[tid] = W2[2 * tid + 1];
        }
        __syncthreads();
        float mp = s_mv[0];
        for (int n = gt0; n < N_NODES; n += TOT) {
            float di = g_dinv[n];
            float pm = di * ldcg(&g_praw[n]) - mp;
            float y0 = 0.f, y1 = 0.f;
            #pragma unroll 16
            for (int c = 0; c < HIDDEN; c++) {
                float h = fmaf(pm, s_a[c], s_b[c]);
                h = fmaxf(h, 0.f);
                y0 = fmaf(h, s_w0[c], y0);
                y1 = fmaf(h, s_w1[c], y1);
            }
            float2 ysc = make_float2(y0 * di, y1 * di);
            g_ysc[n]  = ysc;
            g_araw[n] = ysc;
        }
    }
    gbar(4);

    // ---- P5: araw[dst] += w * ysc[src]  (vector RED) ----
    for (int t = gt0; t < EQ; t += TOT) {
        int4   s4 = reinterpret_cast<const int4*>(src)[t];
        int4   d4 = reinterpret_cast<const int4*>(dst)[t];
        float4 w4 = reinterpret_cast<const float4*>(ew)[t];
        float2 y0 = *(const float2*)__builtin_assume_aligned(&g_ysc[s4.x], 8);
        float2 y1 = g_ysc[s4.y];
        float2 y2 = g_ysc[s4.z];
        float2 y3 = g_ysc[s4.w];
        red_add_v2(&g_araw[d4.x], w4.x * y0.x, w4.x * y0.y);
        red_add_v2(&g_araw[d4.y], w4.y * y1.x, w4.y * y1.y);
        red_add_v2(&g_araw[d4.z], w4.z * y2.x, w4.z * y2.y);
        red_add_v2(&g_araw[d4.w], w4.w * y3.x, w4.w * y3.y);
    }
    gbar(5);

    // ---- P6: pooling partials ----
    {
        if (tid < 2 * N_GRAPHS) ssum[tid] = 0.f;
        if (tid < N_GRAPHS)     scnt[tid] = 0.f;
        __syncthreads();
        for (int n = gt0; n < N_NODES; n += TOT) {
            int g = batch[n];
            float di = g_dinv[n];
            float2 a = ldcg2(&g_araw[n]);
            atomicAdd(&ssum[2 * g],     di * a.x);
            atomicAdd(&ssum[2 * g + 1], di * a.y);
            atomicAdd(&scnt[g], 1.0f);
        }
        __syncthreads();
        if (tid < 2 * N_GRAPHS && ssum[tid] != 0.f) atomicAdd(&g_gsum[tid], ssum[tid]);
        if (tid < N_GRAPHS     && scnt[tid] != 0.f) atomicAdd(&g_gcnt[tid], scnt[tid]);
    }
    gbar(6);

    // ---- P7: finalize (block 0) + reset by last arriver ----
    if (blockIdx.x == 0 && tid < 2 * N_GRAPHS) {
        float cnt = fmaxf(ldcg(&g_gcnt[tid >> 1]), 1.0f);
        out[tid] = ldcg(&g_gsum[tid]) / cnt + b2[tid & 1];
    }
    __syncthreads();              // block0: out-writes precede its arrival
    if (tid == 0) {
        __threadfence();
        if (atomicAdd(&g_bar[7], 1u) == NBLK - 1) {
            // every block has passed all spins; safe to reset everything
            #pragma unroll
            for (int i = 0; i < 8; i++) g_bar[i] = 0u;
            g_stats[0] = 0.f; g_stats[1] = 0.f;
            for (int i = 0; i < 2 * N_GRAPHS; i++) g_gsum[i] = 0.f;
            for (int i = 0; i < N_GRAPHS; i++)     g_gcnt[i] = 0.f;
        }
    }
}

// ---------------- launch ----------------
extern "C" void kernel_launch(void* const* d_in, const int* in_sizes, int n_in,
                              void* d_out, int out_size) {
    const float* x     = (const float*)d_in[0];
    const int*   ei    = (const int*)  d_in[1];
    const float* ew    = (const float*)d_in[2];
    const int*   batch = (const int*)  d_in[3];
    const float* W1    = (const float*)d_in[4];
    const float* gamma = (const float*)d_in[6];
    const float* beta  = (const float*)d_in[7];
    const float* W2    = (const float*)d_in[8];
    const float* b2    = (const float*)d_in[9];

    k_all<<<NBLK, NTHR>>>(x, ei, ei + N_EDGES, ew, batch,
                          W1, gamma, beta, W2, b2, (float*)d_out);
}